// round 1
// baseline (speedup 1.0000x reference)
#include <cuda_runtime.h>
#include <cstdint>
#include <cstddef>

// ---------------------------------------------------------------------------
// Word2vec NCE forward (embed gather + true/sampled logits + sigmoid-xent mean)
//
//   out[0 .. BATCH*EMB)  = embeddings[inputs]           (f32, exact gather)
//   out[BATCH*EMB]       = nce_cost                     (f32 scalar)
//
// Strategy:
//   prep_kernel : detect int32-vs-int64 id encoding, zero the cost accumulator
//   wt_kernel   : gather+transpose samp_w -> g_wt[k][s] (256x256 f32, L2-resident)
//   main_kernel : per block: gather 64 embed rows to smem+out, true-logit dots,
//                 64x256x256 register-tiled GEMM with packed fma.rn.f32x2,
//                 softplus epilogue, per-block partial sum -> atomicAdd
//   fin_kernel  : out[BATCH*EMB] = acc / BATCH
// ---------------------------------------------------------------------------

namespace {
constexpr int VOCAB = 100000;
constexpr int EMB   = 256;
constexpr int NS    = 256;     // NUM_SAMPLED
constexpr int BATCH = 16384;
constexpr int TB    = 64;      // batch rows per block
constexpr int KC    = 32;      // k-chunk staged in smem
constexpr int NWARP = 8;       // 256 threads
}

__device__ float g_wt[EMB * NS];   // wt[k][s] = nce_weights[sampled_ids[s]][k]
__device__ float g_acc;
__device__ int   g_is64;

__device__ __forceinline__ long long load_id(const void* p, int i, int is64) {
    return is64 ? ((const long long*)p)[i] : (long long)((const int*)p)[i];
}

// --------------------------------------------------------------------------
__global__ void prep_kernel(const void* __restrict__ inputs) {
    if (threadIdx.x == 0) {
        // If ids are int64, every odd 32-bit word of the first 16 entries is 0
        // (values < 2^31, non-negative). For int32 data these words are random
        // vocabulary ids; P(all 16 == 0) is negligible.
        const int* p = (const int*)inputs;
        int z = 0;
        #pragma unroll
        for (int i = 0; i < 16; i++) z |= p[2 * i + 1];
        g_is64 = (z == 0) ? 1 : 0;
        g_acc = 0.0f;
    }
}

// gather + transpose sampled weight rows: g_wt[k][s]
__global__ void wt_kernel(const float* __restrict__ ncw,
                          const void* __restrict__ sids) {
    int idx = blockIdx.x * blockDim.x + threadIdx.x;   // 0 .. EMB*NS-1
    int k = idx & (EMB - 1);
    int s = idx >> 8;
    long long row = load_id(sids, s, g_is64);
    g_wt[k * NS + s] = ncw[(size_t)row * EMB + k];
}

// --------------------------------------------------------------------------
__global__ void __launch_bounds__(256, 2)
main_kernel(const float* __restrict__ emb, const float* __restrict__ ncw,
            const float* __restrict__ ncb, const void* __restrict__ inputs,
            const void* __restrict__ labels, const void* __restrict__ sids,
            float* __restrict__ out)
{
    extern __shared__ float smem[];
    float* es   = smem;                 // [TB][EMB]  64 KB
    float* ws   = es + TB * EMB;        // [KC][NS]   32 KB
    float* soff = ws + KC * NS;         // [NS]        1 KB
    float* bsum = soff + NS;            // [NWARP]

    const int tid  = threadIdx.x;
    const int wid  = tid >> 5;
    const int lane = tid & 31;
    const int is64 = g_is64;
    const int b0   = blockIdx.x * TB;

    const float INVL = 1.0f / logf((float)VOCAB + 1.0f);

    // ---- sampled-logit additive offsets: biases[s] - log(NS * prob(s)) ----
    {
        long long id = load_id(sids, tid, is64);
        float p = log1pf(1.0f / (float)(id + 1)) * INVL;  // log-uniform prob
        soff[tid] = ncb[id] - logf((float)NS * p);
    }

    // ---- gather embed rows into smem + write to output ----
    const float4* emb4 = (const float4*)emb;
    float4*       out4 = (float4*)out;
    float4*       es4  = (float4*)es;
    for (int r = wid; r < TB; r += NWARP) {
        long long g = load_id(inputs, b0 + r, is64);
        float4 v0 = emb4[(size_t)g * 64 + lane];
        float4 v1 = emb4[(size_t)g * 64 + 32 + lane];
        es4[r * 64 + lane]      = v0;
        es4[r * 64 + 32 + lane] = v1;
        out4[(size_t)(b0 + r) * 64 + lane]      = v0;
        out4[(size_t)(b0 + r) * 64 + 32 + lane] = v1;
    }
    __syncthreads();

    // ---- true-logit xent: warp `wid` owns rows wid*8 .. wid*8+7 ----
    float tsum = 0.0f;
    const float4* ncw4 = (const float4*)ncw;
    for (int rr = 0; rr < 8; rr++) {
        int r = wid * 8 + rr;
        long long lab = load_id(labels, b0 + r, is64);
        float4 w0 = ncw4[(size_t)lab * 64 + lane];
        float4 w1 = ncw4[(size_t)lab * 64 + 32 + lane];
        float4 e0 = es4[r * 64 + lane];
        float4 e1 = es4[r * 64 + 32 + lane];
        float d = w0.x * e0.x;
        d = fmaf(w0.y, e0.y, d); d = fmaf(w0.z, e0.z, d); d = fmaf(w0.w, e0.w, d);
        d = fmaf(w1.x, e1.x, d); d = fmaf(w1.y, e1.y, d);
        d = fmaf(w1.z, e1.z, d); d = fmaf(w1.w, e1.w, d);
        #pragma unroll
        for (int o = 16; o > 0; o >>= 1) d += __shfl_xor_sync(0xffffffffu, d, o);
        if (lane == 0) {
            float p  = log1pf(1.0f / (float)(lab + 1)) * INVL;
            float tl = d + ncb[lab] - logf((float)NS * p);
            // sigmoid_xent(tl, label=1) = max(tl,0) - tl + log1p(exp(-|tl|))
            tsum += fmaxf(tl, 0.0f) - tl + log1pf(expf(-fabsf(tl)));
        }
    }

    // ---- GEMM: rows wid*8..+7, cols lane*8..+7, packed f32x2 accumulators ----
    unsigned long long acc[8][4];
    #pragma unroll
    for (int i = 0; i < 8; i++)
        #pragma unroll
        for (int j = 0; j < 4; j++) acc[i][j] = 0ull;

    const float4* wt4 = (const float4*)g_wt;
    float4*       ws4 = (float4*)ws;
    const ulonglong2* ws2 = (const ulonglong2*)ws;

    for (int kc = 0; kc < EMB; kc += KC) {
        __syncthreads();
        // stage wt[kc..kc+KC)[*] : KC*NS floats = 2048 float4, 8 per thread
        #pragma unroll
        for (int t = 0; t < (KC * NS / 4) / 256; t++)
            ws4[tid + t * 256] = wt4[kc * (NS / 4) + tid + t * 256];
        __syncthreads();

        #pragma unroll
        for (int kk4 = 0; kk4 < KC / 4; kk4++) {
            float4 av[8];
            #pragma unroll
            for (int rr = 0; rr < 8; rr++)       // broadcast LDS.128 per row
                av[rr] = es4[(wid * 8 + rr) * 64 + (kc >> 2) + kk4];
            #pragma unroll
            for (int u = 0; u < 4; u++) {
                int kk = kk4 * 4 + u;
                ulonglong2 q0 = ws2[kk * 64 + lane * 2];      // cols lane*8+0..3
                ulonglong2 q1 = ws2[kk * 64 + lane * 2 + 1];  // cols lane*8+4..7
                #pragma unroll
                for (int rr = 0; rr < 8; rr++) {
                    float a = (u == 0) ? av[rr].x : (u == 1) ? av[rr].y
                            : (u == 2) ? av[rr].z : av[rr].w;
                    unsigned int ai = __float_as_uint(a);
                    unsigned long long ap;
                    asm("mov.b64 %0, {%1, %1};" : "=l"(ap) : "r"(ai));
                    asm("fma.rn.f32x2 %0, %1, %2, %0;" : "+l"(acc[rr][0]) : "l"(ap), "l"(q0.x));
                    asm("fma.rn.f32x2 %0, %1, %2, %0;" : "+l"(acc[rr][1]) : "l"(ap), "l"(q0.y));
                    asm("fma.rn.f32x2 %0, %1, %2, %0;" : "+l"(acc[rr][2]) : "l"(ap), "l"(q1.x));
                    asm("fma.rn.f32x2 %0, %1, %2, %0;" : "+l"(acc[rr][3]) : "l"(ap), "l"(q1.y));
                }
            }
        }
    }

    // ---- softplus epilogue + row sums + block reduction ----
    float wsum = tsum;
    #pragma unroll
    for (int rr = 0; rr < 8; rr++) {
        float s = 0.0f;
        #pragma unroll
        for (int p2 = 0; p2 < 4; p2++) {
            unsigned int lo, hi;
            asm("mov.b64 {%0, %1}, %2;" : "=r"(lo), "=r"(hi) : "l"(acc[rr][p2]));
            float l0 = __uint_as_float(lo) + soff[lane * 8 + p2 * 2];
            float l1 = __uint_as_float(hi) + soff[lane * 8 + p2 * 2 + 1];
            // sigmoid_xent(l, label=0) = max(l,0) + log1p(exp(-|l|))
            s += fmaxf(l0, 0.0f) + log1pf(expf(-fabsf(l0)));
            s += fmaxf(l1, 0.0f) + log1pf(expf(-fabsf(l1)));
        }
        #pragma unroll
        for (int o = 16; o > 0; o >>= 1) s += __shfl_xor_sync(0xffffffffu, s, o);
        if (lane == 0) wsum += s;
    }
    if (lane == 0) bsum[wid] = wsum;
    __syncthreads();
    if (tid == 0) {
        float t = 0.0f;
        #pragma unroll
        for (int i = 0; i < NWARP; i++) t += bsum[i];
        atomicAdd(&g_acc, t);
    }
}

// --------------------------------------------------------------------------
__global__ void fin_kernel(float* __restrict__ out) {
    out[(size_t)BATCH * EMB] = g_acc * (1.0f / (float)BATCH);
}

// --------------------------------------------------------------------------
extern "C" void kernel_launch(void* const* d_in, const int* in_sizes, int n_in,
                              void* d_out, int out_size) {
    const float* emb    = (const float*)d_in[0];
    const float* ncw    = (const float*)d_in[1];
    const float* ncb    = (const float*)d_in[2];
    const void*  inputs = d_in[3];
    const void*  labels = d_in[4];
    const void*  sids   = d_in[5];
    float* out = (float*)d_out;

    size_t smem = (size_t)(TB * EMB + KC * NS + NS + NWARP) * sizeof(float);
    cudaFuncSetAttribute(main_kernel,
                         cudaFuncAttributeMaxDynamicSharedMemorySize, (int)smem);

    prep_kernel<<<1, 32>>>(inputs);
    wt_kernel<<<(EMB * NS) / 1024, 1024>>>(ncw, sids);
    main_kernel<<<BATCH / TB, 256, smem>>>(emb, ncw, ncb, inputs, labels, sids, out);
    fin_kernel<<<1, 1>>>(out);
}

// round 3
// speedup vs baseline: 3.8077x; 3.8077x over previous
#include <cuda_runtime.h>
#include <cuda_bf16.h>
#include <cstdint>
#include <cstddef>

// ---------------------------------------------------------------------------
// Word2vec NCE forward, mma.sync (HMMA bf16) edition.
//   out[0 .. BATCH*EMB) = embeddings[inputs]   (f32, exact gather)
//   out[BATCH*EMB]      = nce_cost
//
// tcgen05 is unavailable (harness PTX targets plain sm_103, not sm_103a),
// so the sampled-logits GEMM uses arch-portable mma.m16n8k16.bf16 + ldmatrix.
//
// 2 launches:
//   prep_wt : reset accumulators; gather samp_w rows -> g_wtb (bf16 [s][k])
//   main    : per block (128 batch rows, 512 threads):
//             gather embed rows -> out(f32) + smem A (bf16, swizzled)
//             copy g_wtb -> smem B (bf16, swizzled)
//             16-warp HMMA GEMM 128x256x256 (warp tile 32x64)
//             true-logit dots on CUDA cores
//             softplus epilogue on register c-frags -> atomicAdd
//             last block writes out[BATCH*EMB]
// ---------------------------------------------------------------------------

namespace {
constexpr int VOCAB = 100000;
constexpr int EMB   = 256;
constexpr int NS    = 256;
constexpr int BATCH = 16384;
constexpr int TB    = 128;               // batch rows per block
constexpr int NBLK  = BATCH / TB;        // 128 blocks
constexpr int NTHR  = 512;               // 16 warps

// smem byte map
constexpr int SM_A    = 0;               // A: 128 x 256 bf16 = 64 KB (swizzled)
constexpr int SM_B    = 65536;           // B: 256 x 256 bf16 = 128 KB (swizzled)
constexpr int SM_SOFF = 196608;          // soff[256] f32
constexpr int SM_WSUM = 197632;          // 16 warp partial sums
constexpr int SM_TOT  = 197632 + 64;
}

__device__ __nv_bfloat16 g_wtb[NS * EMB];   // sampled weights, [s][k] bf16
__device__ float    g_acc;
__device__ unsigned g_done;

// ---------------------------------------------------------------------------
__device__ __forceinline__ long long load_id(const void* p, int i, int is64) {
    return is64 ? ((const long long*)p)[i] : (long long)((const int*)p)[i];
}
__device__ __forceinline__ int detect_is64(const void* p) {
    const int* q = (const int*)p;
    int z = 0;
    #pragma unroll
    for (int i = 0; i < 16; i++) z |= q[2 * i + 1];
    return (z == 0) ? 1 : 0;
}
__device__ __forceinline__ uint32_t smem_u32(const void* p) {
    uint32_t a;
    asm("{ .reg .u64 t; cvta.to.shared.u64 t, %1; cvt.u32.u64 %0, t; }"
        : "=r"(a) : "l"(p));
    return a;
}
// swizzled byte offset inside a [row][256 bf16] tile (512 B rows, 16B chunks)
__device__ __forceinline__ uint32_t sw_off(int row, int chunk) {
    return (uint32_t)row * 512u + (uint32_t)((chunk ^ (row & 7)) << 4);
}

__device__ __forceinline__ void ldsm_x4(uint32_t addr, uint32_t* r) {
    asm volatile("ldmatrix.sync.aligned.m8n8.x4.shared.b16 {%0,%1,%2,%3}, [%4];"
        : "=r"(r[0]), "=r"(r[1]), "=r"(r[2]), "=r"(r[3]) : "r"(addr));
}
__device__ __forceinline__ void ldsm_x2(uint32_t addr, uint32_t* r) {
    asm volatile("ldmatrix.sync.aligned.m8n8.x2.shared.b16 {%0,%1}, [%2];"
        : "=r"(r[0]), "=r"(r[1]) : "r"(addr));
}
__device__ __forceinline__ void mma_bf16(float* c, const uint32_t* a,
                                         const uint32_t* b) {
    asm volatile(
        "mma.sync.aligned.m16n8k16.row.col.f32.bf16.bf16.f32 "
        "{%0,%1,%2,%3}, {%4,%5,%6,%7}, {%8,%9}, {%0,%1,%2,%3};"
        : "+f"(c[0]), "+f"(c[1]), "+f"(c[2]), "+f"(c[3])
        : "r"(a[0]), "r"(a[1]), "r"(a[2]), "r"(a[3]), "r"(b[0]), "r"(b[1]));
}
__device__ __forceinline__ float softplus_neg(float ax) {
    // log1p(exp(-ax)) for ax >= 0
    return __logf(1.0f + __expf(-ax));
}

// ---------------------------------------------------------------------------
__global__ void prep_wt_kernel(const float* __restrict__ ncw,
                               const void* __restrict__ sids) {
    __shared__ int s_is64;
    if (threadIdx.x == 0) {
        s_is64 = detect_is64(sids);
        if (blockIdx.x == 0) { g_acc = 0.0f; g_done = 0u; }
    }
    __syncthreads();
    int t = blockIdx.x * blockDim.x + threadIdx.x;   // 0 .. NS*EMB-1
    int s = t >> 8, k = t & 255;
    long long id = load_id(sids, s, s_is64);
    g_wtb[s * EMB + k] = __float2bfloat16(ncw[(size_t)id * EMB + k]);
}

// ---------------------------------------------------------------------------
__global__ void __launch_bounds__(NTHR, 1)
main_kernel(const float* __restrict__ emb, const float* __restrict__ ncw,
            const float* __restrict__ ncb, const void* __restrict__ inputs,
            const void* __restrict__ labels, const void* __restrict__ sids,
            float* __restrict__ out)
{
    extern __shared__ __align__(1024) char smem[];
    const uint32_t smb = smem_u32(smem);
    const int tid  = threadIdx.x;
    const int wid  = tid >> 5;
    const int lane = tid & 31;
    const int b0   = blockIdx.x * TB;
    const int is64 = detect_is64(inputs);
    const float INVL = 1.0f / logf((float)VOCAB + 1.0f);

    // ---- sampled-logit offsets: biases[s] - log(NS * prob(s))
    if (tid < NS) {
        long long id = load_id(sids, tid, is64);
        float fid = (float)id;
        float p = (logf(fid + 2.0f) - logf(fid + 1.0f)) * INVL;
        ((float*)(smem + SM_SOFF))[tid] = ncb[id] - logf((float)NS * p);
    }

    // ---- B tile: g_wtb [s][k] bf16 -> smem swizzled
    {
        const uint4* src = (const uint4*)g_wtb;
        #pragma unroll
        for (int i = 0; i < 16; i++) {
            int t = tid + i * NTHR;               // 0..8191 16B chunks
            int s = t >> 5, c = t & 31;
            *(uint4*)(smem + SM_B + sw_off(s, c)) = src[t];
        }
    }

    // ---- A tile: gather embed rows -> out (f32) + smem (bf16 swizzled)
    {
        int r    = tid >> 2;                      // 4 threads per row
        int part = tid & 3;                       // 64 k each
        long long g = load_id(inputs, b0 + r, is64);
        const float4* src = (const float4*)emb + (size_t)g * 64 + part * 16;
        float4*       dst = (float4*)out + (size_t)(b0 + r) * 64 + part * 16;
        #pragma unroll
        for (int i = 0; i < 16; i++) {
            float4 v = src[i];
            dst[i] = v;
            __nv_bfloat162 lo = __floats2bfloat162_rn(v.x, v.y);
            __nv_bfloat162 hi = __floats2bfloat162_rn(v.z, v.w);
            uint2 u;
            u.x = *(uint32_t*)&lo;
            u.y = *(uint32_t*)&hi;
            int k0 = part * 64 + i * 4;
            *(uint2*)(smem + SM_A + sw_off(r, k0 >> 3) + ((k0 & 7) << 1)) = u;
        }
    }
    __syncthreads();

    // ---- true-logit xent: warp wid owns rows wid*8 .. +7
    float tsum = 0.0f;
    {
        const float4* ncw4 = (const float4*)ncw;
        #pragma unroll
        for (int rr = 0; rr < 8; rr++) {
            int r = wid * 8 + rr;
            long long lab = load_id(labels, b0 + r, is64);
            float4 w0 = ncw4[(size_t)lab * 64 + lane * 2];
            float4 w1 = ncw4[(size_t)lab * 64 + lane * 2 + 1];
            uint4 eu = *(const uint4*)(smem + SM_A + sw_off(r, lane));
            float2 e0 = __bfloat1622float2(*(__nv_bfloat162*)&eu.x);
            float2 e1 = __bfloat1622float2(*(__nv_bfloat162*)&eu.y);
            float2 e2 = __bfloat1622float2(*(__nv_bfloat162*)&eu.z);
            float2 e3 = __bfloat1622float2(*(__nv_bfloat162*)&eu.w);
            float d = e0.x * w0.x;
            d = fmaf(e0.y, w0.y, d); d = fmaf(e1.x, w0.z, d); d = fmaf(e1.y, w0.w, d);
            d = fmaf(e2.x, w1.x, d); d = fmaf(e2.y, w1.y, d);
            d = fmaf(e3.x, w1.z, d); d = fmaf(e3.y, w1.w, d);
            #pragma unroll
            for (int o = 16; o > 0; o >>= 1) d += __shfl_xor_sync(0xffffffffu, d, o);
            if (lane == 0) {
                float fl = (float)lab;
                float p  = (logf(fl + 2.0f) - logf(fl + 1.0f)) * INVL;
                float tl = d + ncb[lab] - logf((float)NS * p);
                tsum += fmaxf(tl, 0.0f) - tl + softplus_neg(fabsf(tl));
            }
        }
    }

    // ---- HMMA GEMM: warp grid 4m x 4n, warp tile 32 x 64
    const int wm = wid & 3;                  // row group
    const int wn = wid >> 2;                 // col group
    float acc[2][8][4];
    #pragma unroll
    for (int mt = 0; mt < 2; mt++)
        #pragma unroll
        for (int nt = 0; nt < 8; nt++)
            #pragma unroll
            for (int j = 0; j < 4; j++) acc[mt][nt][j] = 0.0f;

    // per-lane ldmatrix source rows
    const int amat  = lane >> 3;                       // 0..3
    const int arow0 = wm * 32 +      ((amat & 1) << 3) + (lane & 7);
    const int arow1 = arow0 + 16;
    const int aext  = amat >> 1;                       // k-chunk +0/+1
    const uint32_t abase0 = smb + SM_A + (uint32_t)arow0 * 512u;
    const uint32_t abase1 = smb + SM_A + (uint32_t)arow1 * 512u;
    const int     axor0  = arow0 & 7, axor1 = arow1 & 7;

    const int li    = lane & 15;
    const int bhalf = li >> 3;                         // k-chunk +0/+1
    const int brow  = wn * 64 + (li & 7);              // n row (nt adds 8*nt)
    const uint32_t bbase = smb + SM_B + (uint32_t)brow * 512u;
    const int     bxor  = brow & 7;

    #pragma unroll
    for (int ks = 0; ks < 16; ks++) {
        uint32_t a0[4], a1[4];
        int ac = ks * 2 + aext;
        ldsm_x4(abase0 + (uint32_t)((ac ^ axor0) << 4), a0);
        ldsm_x4(abase1 + (uint32_t)((ac ^ axor1) << 4), a1);
        int bc = ks * 2 + bhalf;
        uint32_t boff = (uint32_t)((bc ^ bxor) << 4);
        #pragma unroll
        for (int nt = 0; nt < 8; nt++) {
            uint32_t b[2];
            ldsm_x2(bbase + (uint32_t)nt * 4096u + boff, b);
            mma_bf16(acc[0][nt], a0, b);
            mma_bf16(acc[1][nt], a1, b);
        }
    }

    // ---- softplus epilogue on c-frags
    const float* soff = (const float*)(smem + SM_SOFF);
    float ssum = 0.0f;
    {
        const int colb = wn * 64 + ((lane & 3) << 1);
        #pragma unroll
        for (int nt = 0; nt < 8; nt++) {
            float s0 = soff[colb + nt * 8];
            float s1 = soff[colb + nt * 8 + 1];
            #pragma unroll
            for (int mt = 0; mt < 2; mt++) {
                float l0 = acc[mt][nt][0] + s0;
                float l1 = acc[mt][nt][1] + s1;
                float l2 = acc[mt][nt][2] + s0;
                float l3 = acc[mt][nt][3] + s1;
                ssum += fmaxf(l0, 0.0f) + softplus_neg(fabsf(l0));
                ssum += fmaxf(l1, 0.0f) + softplus_neg(fabsf(l1));
                ssum += fmaxf(l2, 0.0f) + softplus_neg(fabsf(l2));
                ssum += fmaxf(l3, 0.0f) + softplus_neg(fabsf(l3));
            }
        }
    }

    // ---- reduce: warp -> block -> global
    float wsum = ssum + tsum;
    #pragma unroll
    for (int o = 16; o > 0; o >>= 1) wsum += __shfl_xor_sync(0xffffffffu, wsum, o);
    if (lane == 0) ((float*)(smem + SM_WSUM))[wid] = wsum;
    __syncthreads();

    if (tid == 0) {
        float t = 0.0f;
        #pragma unroll
        for (int i = 0; i < 16; i++) t += ((float*)(smem + SM_WSUM))[i];
        atomicAdd(&g_acc, t);
        __threadfence();
        unsigned cnt = atomicAdd(&g_done, 1u);
        if (cnt == (unsigned)(NBLK - 1)) {
            __threadfence();
            out[(size_t)BATCH * EMB] = g_acc * (1.0f / (float)BATCH);
        }
    }
}

// ---------------------------------------------------------------------------
extern "C" void kernel_launch(void* const* d_in, const int* in_sizes, int n_in,
                              void* d_out, int out_size) {
    const float* emb    = (const float*)d_in[0];
    const float* ncw    = (const float*)d_in[1];
    const float* ncb    = (const float*)d_in[2];
    const void*  inputs = d_in[3];
    const void*  labels = d_in[4];
    const void*  sids   = d_in[5];
    float* out = (float*)d_out;

    cudaFuncSetAttribute(main_kernel,
                         cudaFuncAttributeMaxDynamicSharedMemorySize, SM_TOT);

    prep_wt_kernel<<<(NS * EMB) / 1024, 1024>>>(ncw, sids);
    main_kernel<<<NBLK, NTHR, SM_TOT>>>(emb, ncw, ncb, inputs, labels, sids, out);
}